// round 4
// baseline (speedup 1.0000x reference)
#include <cuda_runtime.h>
#include <stdint.h>

// FullMultiEmbedding fused single-pass:
//   out[b, e, :] = weight[e, :] * psw[i]   if e == input_[i] for some i in bag b
//                = 0                        otherwise
// Output [B, NUM_EMB, D] fp32 (D=64). Purely HBM-write-bound (655 MB).
//
// Inputs (metadata order; JAX x64 disabled -> "int64" arrays are int32):
//   d_in[0] input_             int32  [L]   (12800)
//   d_in[1] offsets            int32  [B]   (256)
//   d_in[2] per_sample_weights float32 [L]
//   d_in[3] weight             float32 [NUM_EMB, D] (10000 x 64)

static constexpr int D4 = 16;        // 64 floats = 16 float4 per row
static constexpr int SPLITS = 18;    // row-slices per bag -> B*SPLITS = 4608 blocks
static constexpr int THREADS = 256;  // 16 rows of 16 float4-lanes per iteration

__global__ void fused_kernel(const int* __restrict__ input_,
                             const int* __restrict__ offsets,
                             const float* __restrict__ psw,
                             const float4* __restrict__ weight,
                             float4* __restrict__ out,
                             int L, int B, int num_emb, int rows_per_slice) {
    extern __shared__ uint32_t bm[];   // membership bitmap, (num_emb+31)/32 words

    const int bag   = blockIdx.x / SPLITS;
    const int slice = blockIdx.x % SPLITS;

    const int off = offsets[bag];
    const int end = (bag + 1 < B) ? offsets[bag + 1] : L;
    const int len = end - off;

    // --- build bag membership bitmap in SMEM ---
    const int bm_words = (num_emb + 31) >> 5;
    for (int w = threadIdx.x; w < bm_words; w += THREADS) bm[w] = 0u;
    __syncthreads();
    for (int j = threadIdx.x; j < len; j += THREADS) {
        int e = input_[off + j];
        if (e >= 0 && e < num_emb) atomicOr(&bm[e >> 5], 1u << (e & 31));
    }
    __syncthreads();

    // --- stream this slice's rows: zero or weighted-embedding ---
    const int e0 = slice * rows_per_slice;
    const int e1 = min(e0 + rows_per_slice, num_emb);
    const int d4 = threadIdx.x & 15;        // float4 lane within the row
    const int r  = threadIdx.x >> 4;        // row within this iteration (0..15)
    const long long bag_base = (long long)bag * num_emb;

    for (int e = e0 + r; e < e1; e += 16) {
        float4 v = make_float4(0.f, 0.f, 0.f, 0.f);
        if (bm[e >> 5] & (1u << (e & 31))) {
            // rare path (~50 rows per bag): recover flat index i, last match wins
            float w = 0.f;
            for (int j = 0; j < len; j++) {
                if (input_[off + j] == e) w = psw[off + j];
            }
            v = weight[(long long)e * D4 + d4];
            v.x *= w; v.y *= w; v.z *= w; v.w *= w;
        }
        out[(bag_base + e) * D4 + d4] = v;
    }
}

extern "C" void kernel_launch(void* const* d_in, const int* in_sizes, int n_in,
                              void* d_out, int out_size) {
    const int*   input_  = (const int*)d_in[0];
    const int*   offsets = (const int*)d_in[1];
    const float* psw     = (const float*)d_in[2];
    const float* weight  = (const float*)d_in[3];
    float* out = (float*)d_out;

    const int L = in_sizes[0];
    const int B = in_sizes[1];
    const int num_emb = in_sizes[3] / 64;

    const int rows_per_slice = (num_emb + SPLITS - 1) / SPLITS;
    const int blocks = B * SPLITS;
    const size_t smem = ((num_emb + 31) / 32) * sizeof(uint32_t);

    fused_kernel<<<blocks, THREADS, smem>>>(input_, offsets, psw,
                                            (const float4*)weight,
                                            (float4*)out,
                                            L, B, num_emb, rows_per_slice);
}

// round 5
// speedup vs baseline: 1.0486x; 1.0486x over previous
#include <cuda_runtime.h>
#include <stdint.h>

// FullMultiEmbedding fused single-pass:
//   out[b, e, :] = weight[e, :] * psw[i]  if e == input_[i] for some i in bag b
//                = 0                       otherwise
// Output [B, NUM_EMB, D] fp32 (D=64), 655 MB -> purely HBM-write-bound.
//
// Inputs (JAX x64 disabled -> "int64" arrays are int32 on the wire):
//   d_in[0] input_             int32   [L]   (12800)
//   d_in[1] offsets            int32   [B]   (256)
//   d_in[2] per_sample_weights float32 [L]
//   d_in[3] weight             float32 [NUM_EMB, 64] (10000 x 64)
//
// Fast path: each bag's indices form a consecutive run (start+j) % num_emb.
// This is VERIFIED per block; membership then costs 2 integer ops per row.
// Fallback (arbitrary data): linear scan of the bag's index list in SMEM.

static constexpr int D4      = 16;   // 64 floats = 16 float4 per row
static constexpr int SPLITS  = 18;   // row-slices per bag -> 256*18 = 4608 blocks
static constexpr int THREADS = 256;  // 16 rows x 16 float4-lanes per iteration
static constexpr int CAP     = 2048; // SMEM cache for bag indices (fallback path)

__global__ void __launch_bounds__(THREADS) fused_kernel(
        const int* __restrict__ input_,
        const int* __restrict__ offsets,
        const float* __restrict__ psw,
        const float4* __restrict__ weight,
        float4* __restrict__ out,
        int L, int B, int num_emb, int rows_per_slice) {
    __shared__ int   e_list[CAP];
    __shared__ float w_list[CAP];
    __shared__ int   s_consec;

    const int bag   = blockIdx.x / SPLITS;
    const int slice = blockIdx.x % SPLITS;

    const int off = offsets[bag];
    const int end = (bag + 1 < B) ? offsets[bag + 1] : L;
    const int len = end - off;
    const int start = (len > 0) ? input_[off] : 0;
    const bool cache = (len <= CAP);

    if (threadIdx.x == 0) s_consec = 1;
    __syncthreads();
    for (int j = threadIdx.x; j < len; j += THREADS) {
        int e = input_[off + j];
        if (cache) { e_list[j] = e; w_list[j] = psw[off + j]; }
        int expect = start + j;
        if (expect >= num_emb) expect -= num_emb;
        if (e != expect) s_consec = 0;   // any-thread clear; barrier below
    }
    __syncthreads();
    const bool consec = (s_consec != 0) && cache;

    // ---- stream this slice's rows ----
    const int e0 = slice * rows_per_slice;
    const int e1 = min(e0 + rows_per_slice, num_emb);
    const int d4 = threadIdx.x & 15;   // float4 lane in row
    const int r  = threadIdx.x >> 4;   // row within iteration (0..15)

    int e = e0 + r;
    if (e >= e1) return;

    // distance from run start, kept in [0, num_emb)
    int d = e - start;
    if (d < 0) d += num_emb;

    // 32-bit float4 indexing (max ~41M < 2^31)
    float4* p = out + ((unsigned)(bag * num_emb + e) * D4 + d4);
    const float4 z = make_float4(0.f, 0.f, 0.f, 0.f);

    if (consec) {
        #pragma unroll 4
        for (; e < e1; e += 16) {
            if (d < len) {
                // rare path: ~50 rows/bag
                float w = w_list[d];
                float4 v = weight[(unsigned)e * D4 + d4];
                v.x *= w; v.y *= w; v.z *= w; v.w *= w;
                *p = v;
            } else {
                *p = z;
            }
            d += 16; if (d >= num_emb) d -= num_emb;
            p += 16 * D4;
        }
    } else {
        // general fallback: scan the bag's indices (last match wins)
        for (; e < e1; e += 16) {
            float w = 0.f; bool hit = false;
            if (cache) {
                for (int j = 0; j < len; j++)
                    if (e_list[j] == e) { w = w_list[j]; hit = true; }
            } else {
                for (int j = 0; j < len; j++)
                    if (input_[off + j] == e) { w = psw[off + j]; hit = true; }
            }
            float4 v = z;
            if (hit) {
                v = weight[(unsigned)e * D4 + d4];
                v.x *= w; v.y *= w; v.z *= w; v.w *= w;
            }
            *p = v;
            p += 16 * D4;
        }
    }
}

extern "C" void kernel_launch(void* const* d_in, const int* in_sizes, int n_in,
                              void* d_out, int out_size) {
    const int*   input_  = (const int*)d_in[0];
    const int*   offsets = (const int*)d_in[1];
    const float* psw     = (const float*)d_in[2];
    const float* weight  = (const float*)d_in[3];
    float* out = (float*)d_out;

    const int L = in_sizes[0];
    const int B = in_sizes[1];
    const int num_emb = in_sizes[3] / 64;

    const int rows_per_slice = (num_emb + SPLITS - 1) / SPLITS;
    const int blocks = B * SPLITS;

    fused_kernel<<<blocks, THREADS>>>(input_, offsets, psw,
                                      (const float4*)weight,
                                      (float4*)out,
                                      L, B, num_emb, rows_per_slice);
}